// round 4
// baseline (speedup 1.0000x reference)
#include <cuda_runtime.h>
#include <cuda_bf16.h>
#include <cuda_fp16.h>
#include <math.h>
#include <stddef.h>
#include <stdint.h>

#define N_NODES 50000
#define N_EDGES 800000
#define IN_FEATS 256
#define HD 256          // NUM_HEADS * OUT_FEATS
#define NUM_HEADS 8
#define OUT_FEATS 32
#define NUM_ET 5

// ---------------- scratch (static device globals; no allocation) ----------
__device__ __half g_feat_src[(size_t)N_NODES * HD];         // 25.6 MB (fp16)
__device__ int    g_cnt[(size_t)N_NODES * NUM_ET];          // 1 MB
__device__ float  g_w[(size_t)N_NODES * NUM_ET * NUM_HEADS];// 8 MB
__device__ int    g_off[N_NODES];
__device__ int    g_deg[N_NODES];
__device__ int    g_cur[N_NODES];
__device__ int    g_csr[N_EDGES];
__device__ int    g_total;

// =====================================================================
// 1) GEMM: C[M,256](fp16) = A[M,256]*B[256,256]^T, split-bf16 x3 MMA.
//    BM=128, BN=64, BK=32, 256 threads, 8 warps (4Mx2N), warp 32x32.
// =====================================================================
__device__ __forceinline__ void mma_bf16(float* c, const uint32_t* a, const uint32_t* b) {
    asm volatile(
        "mma.sync.aligned.m16n8k16.row.col.f32.bf16.bf16.f32 "
        "{%0,%1,%2,%3},{%4,%5,%6,%7},{%8,%9},{%0,%1,%2,%3};\n"
        : "+f"(c[0]), "+f"(c[1]), "+f"(c[2]), "+f"(c[3])
        : "r"(a[0]), "r"(a[1]), "r"(a[2]), "r"(a[3]), "r"(b[0]), "r"(b[1]));
}

__device__ __forceinline__ void split_store(__nv_bfloat16* ph, __nv_bfloat16* pl, float4 v) {
    __nv_bfloat162 h01, h23, l01, l23;
    h01.x = __float2bfloat16(v.x);
    h01.y = __float2bfloat16(v.y);
    h23.x = __float2bfloat16(v.z);
    h23.y = __float2bfloat16(v.w);
    l01.x = __float2bfloat16(v.x - __bfloat162float(h01.x));
    l01.y = __float2bfloat16(v.y - __bfloat162float(h01.y));
    l23.x = __float2bfloat16(v.z - __bfloat162float(h23.x));
    l23.y = __float2bfloat16(v.w - __bfloat162float(h23.y));
    *(__nv_bfloat162*)(ph)     = h01;
    *(__nv_bfloat162*)(ph + 2) = h23;
    *(__nv_bfloat162*)(pl)     = l01;
    *(__nv_bfloat162*)(pl + 2) = l23;
}

__global__ __launch_bounds__(256) void gemm_bf16x3_kernel(
    const float* __restrict__ A, const float* __restrict__ B,
    __half* __restrict__ C, int M) {
    __shared__ __nv_bfloat16 As_h[128][40], As_l[128][40];
    __shared__ __nv_bfloat16 Bs_h[64][40],  Bs_l[64][40];

    const int tid = threadIdx.x;
    const int m0 = blockIdx.x * 128;
    const int n0 = blockIdx.y * 64;
    const int warp = tid >> 5, lane = tid & 31;
    const int wm0 = (warp >> 1) * 32, wn0 = (warp & 1) * 32;
    const int g = lane >> 2, tg = lane & 3;

    float acc[2][4][4];
#pragma unroll
    for (int i = 0; i < 2; i++)
#pragma unroll
        for (int j = 0; j < 4; j++)
#pragma unroll
            for (int q = 0; q < 4; q++) acc[i][j][q] = 0.f;

    for (int k0 = 0; k0 < 256; k0 += 32) {
#pragma unroll
        for (int r = 0; r < 4; r++) {
            int idx = tid + r * 256;
            int row = idx >> 3, c4 = (idx & 7) * 4;
            float4 v = make_float4(0.f, 0.f, 0.f, 0.f);
            if (m0 + row < M)
                v = __ldg((const float4*)(A + (size_t)(m0 + row) * 256 + k0 + c4));
            split_store(&As_h[row][c4], &As_l[row][c4], v);
        }
#pragma unroll
        for (int r = 0; r < 2; r++) {
            int idx = tid + r * 256;
            int row = idx >> 3, c4 = (idx & 7) * 4;
            float4 v = __ldg((const float4*)(B + (size_t)(n0 + row) * 256 + k0 + c4));
            split_store(&Bs_h[row][c4], &Bs_l[row][c4], v);
        }
        __syncthreads();

#pragma unroll
        for (int kf = 0; kf < 2; kf++) {
            const int kA = kf * 16 + tg * 2;
            uint32_t ah[2][4], al[2][4], bh[4][2], bl[4][2];
#pragma unroll
            for (int i = 0; i < 2; i++) {
                int r0 = wm0 + i * 16 + g;
                ah[i][0] = *(const uint32_t*)&As_h[r0][kA];
                ah[i][1] = *(const uint32_t*)&As_h[r0 + 8][kA];
                ah[i][2] = *(const uint32_t*)&As_h[r0][kA + 8];
                ah[i][3] = *(const uint32_t*)&As_h[r0 + 8][kA + 8];
                al[i][0] = *(const uint32_t*)&As_l[r0][kA];
                al[i][1] = *(const uint32_t*)&As_l[r0 + 8][kA];
                al[i][2] = *(const uint32_t*)&As_l[r0][kA + 8];
                al[i][3] = *(const uint32_t*)&As_l[r0 + 8][kA + 8];
            }
#pragma unroll
            for (int j = 0; j < 4; j++) {
                int c0 = wn0 + j * 8 + g;
                bh[j][0] = *(const uint32_t*)&Bs_h[c0][kA];
                bh[j][1] = *(const uint32_t*)&Bs_h[c0][kA + 8];
                bl[j][0] = *(const uint32_t*)&Bs_l[c0][kA];
                bl[j][1] = *(const uint32_t*)&Bs_l[c0][kA + 8];
            }
#pragma unroll
            for (int i = 0; i < 2; i++)
#pragma unroll
                for (int j = 0; j < 4; j++) {
                    mma_bf16(acc[i][j], ah[i], bh[j]);
                    mma_bf16(acc[i][j], ah[i], bl[j]);
                    mma_bf16(acc[i][j], al[i], bh[j]);
                }
        }
        __syncthreads();
    }

#pragma unroll
    for (int i = 0; i < 2; i++)
#pragma unroll
        for (int j = 0; j < 4; j++) {
            int m_lo = m0 + wm0 + i * 16 + g;
            int col  = n0 + wn0 + j * 8 + tg * 2;
            if (m_lo < M)
                *(__half2*)(C + (size_t)m_lo * 256 + col) =
                    __floats2half2_rn(acc[i][j][0], acc[i][j][1]);
            if (m_lo + 8 < M)
                *(__half2*)(C + (size_t)(m_lo + 8) * 256 + col) =
                    __floats2half2_rn(acc[i][j][2], acc[i][j][3]);
        }
}

// ---------------- 2) histogram, 4 edges/thread (+ clear g_total) ----------
__global__ void count_kernel(const int* __restrict__ dst,
                             const int* __restrict__ ef) {
    int t4 = blockIdx.x * blockDim.x + threadIdx.x;
    if (t4 == 0) g_total = 0;
    int e = t4 * 4;
    if (e + 4 <= N_EDGES) {
        int4 d = *(const int4*)(dst + e);
        int4 t = *(const int4*)(ef + e);
        atomicAdd(&g_cnt[(size_t)d.x * NUM_ET + t.x], 1);
        atomicAdd(&g_cnt[(size_t)d.y * NUM_ET + t.y], 1);
        atomicAdd(&g_cnt[(size_t)d.z * NUM_ET + t.z], 1);
        atomicAdd(&g_cnt[(size_t)d.w * NUM_ET + t.w], 1);
    } else {
        for (; e < N_EDGES; e++)
            atomicAdd(&g_cnt[(size_t)dst[e] * NUM_ET + ef[e]], 1);
    }
}

// ---------------- 3) fused CSR offsets + per-node softmax table -----------
__global__ void offsets_softmax_kernel(const float* __restrict__ emb) {
    int n = blockIdx.x * blockDim.x + threadIdx.x;
    int lane = threadIdx.x & 31;

    int c[NUM_ET];
    int deg = 0;
    if (n < N_NODES) {
#pragma unroll
        for (int t = 0; t < NUM_ET; t++) {
            c[t] = g_cnt[(size_t)n * NUM_ET + t];
            deg += c[t];
        }
    }
    int incl = deg;
#pragma unroll
    for (int o = 1; o < 32; o <<= 1) {
        int v = __shfl_up_sync(0xffffffffu, incl, o);
        if (lane >= o) incl += v;
    }
    int total = __shfl_sync(0xffffffffu, incl, 31);
    int base = 0;
    if (lane == 0) base = atomicAdd(&g_total, total);
    base = __shfl_sync(0xffffffffu, base, 0);

    if (n < N_NODES) {
        int off = base + incl - deg;
        g_off[n] = off;
        g_cur[n] = off;
        g_deg[n] = deg;

#pragma unroll
        for (int h = 0; h < NUM_HEADS; h++) {
            float ev[NUM_ET];
            float m = -INFINITY;
#pragma unroll
            for (int t = 0; t < NUM_ET; t++) {
                ev[t] = __ldg(emb + t * NUM_HEADS + h);
                if (c[t] > 0) m = fmaxf(m, ev[t]);
            }
            float ex[NUM_ET];
            float denom = 0.f;
#pragma unroll
            for (int t = 0; t < NUM_ET; t++) {
                ex[t] = expf(ev[t] - m);
                denom += (float)c[t] * ex[t];
            }
            float inv = 1.f / denom;   // NaN only for deg==0 nodes (unread)
#pragma unroll
            for (int t = 0; t < NUM_ET; t++)
                g_w[((size_t)n * NUM_ET + t) * NUM_HEADS + h] = ex[t] * inv;
        }
    }
}

// ---------------- 4) scatter to CSR + attn, 4 edges/thread ----------------
__global__ void scatter_attn_kernel(const int* __restrict__ src,
                                    const int* __restrict__ dst,
                                    const int* __restrict__ ef,
                                    float* __restrict__ attn_out) {
    int t4 = blockIdx.x * blockDim.x + threadIdx.x;
    int e = t4 * 4;
    if (e + 4 > N_EDGES) {
        for (; e < N_EDGES; e++) {
            int s = src[e], d = dst[e], t = ef[e];
            int pos = atomicAdd(&g_cur[d], 1);
            g_csr[pos] = s | (t << 16);
            const float4* w4 = (const float4*)(g_w + ((size_t)d * NUM_ET + t) * NUM_HEADS);
            float4* ao = (float4*)(attn_out + (size_t)e * NUM_HEADS);
            ao[0] = __ldg(w4);
            ao[1] = __ldg(w4 + 1);
        }
        return;
    }
    int4 s = *(const int4*)(src + e);
    int4 d = *(const int4*)(dst + e);
    int4 t = *(const int4*)(ef + e);

    // issue 4 independent atomics first (latency overlap)
    int p0 = atomicAdd(&g_cur[d.x], 1);
    int p1 = atomicAdd(&g_cur[d.y], 1);
    int p2 = atomicAdd(&g_cur[d.z], 1);
    int p3 = atomicAdd(&g_cur[d.w], 1);

    // 4 independent attn-weight gathers
    const float4* w0 = (const float4*)(g_w + ((size_t)d.x * NUM_ET + t.x) * NUM_HEADS);
    const float4* w1 = (const float4*)(g_w + ((size_t)d.y * NUM_ET + t.y) * NUM_HEADS);
    const float4* w2 = (const float4*)(g_w + ((size_t)d.z * NUM_ET + t.z) * NUM_HEADS);
    const float4* w3 = (const float4*)(g_w + ((size_t)d.w * NUM_ET + t.w) * NUM_HEADS);
    float4 a00 = __ldg(w0), a01 = __ldg(w0 + 1);
    float4 a10 = __ldg(w1), a11 = __ldg(w1 + 1);
    float4 a20 = __ldg(w2), a21 = __ldg(w2 + 1);
    float4 a30 = __ldg(w3), a31 = __ldg(w3 + 1);

    g_csr[p0] = s.x | (t.x << 16);
    g_csr[p1] = s.y | (t.y << 16);
    g_csr[p2] = s.z | (t.z << 16);
    g_csr[p3] = s.w | (t.w << 16);

    float4* ao = (float4*)(attn_out + (size_t)e * NUM_HEADS);
    ao[0] = a00; ao[1] = a01;
    ao[2] = a10; ao[3] = a11;
    ao[4] = a20; ao[5] = a21;
    ao[6] = a30; ao[7] = a31;
}

// ---------------- 5) CSR aggregation: 1 warp/dst, fp16 gather -------------
__global__ __launch_bounds__(256) void agg_csr_kernel(float* __restrict__ rst) {
    __shared__ float sw[8][NUM_ET * NUM_HEADS];
    const int warp = threadIdx.x >> 5;
    const int lane = threadIdx.x & 31;
    const int d = blockIdx.x * 8 + warp;
    if (d >= N_NODES) return;

    sw[warp][lane] = g_w[(size_t)d * 40 + lane];
    if (lane < 8) sw[warp][32 + lane] = g_w[(size_t)d * 40 + 32 + lane];
    __syncwarp();

    const int off = g_off[d];
    const int deg = g_deg[d];
    const int h0 = lane >> 2;
    const uint4* base = (const uint4*)g_feat_src;

    float acc[8];
#pragma unroll
    for (int q = 0; q < 8; q++) acc[q] = 0.f;

    int i = 0;
    for (; i + 4 <= deg; i += 4) {
        int p0 = g_csr[off + i];
        int p1 = g_csr[off + i + 1];
        int p2 = g_csr[off + i + 2];
        int p3 = g_csr[off + i + 3];
        uint4 v0 = __ldg(base + (size_t)(p0 & 0xFFFF) * 32 + lane);
        uint4 v1 = __ldg(base + (size_t)(p1 & 0xFFFF) * 32 + lane);
        uint4 v2 = __ldg(base + (size_t)(p2 & 0xFFFF) * 32 + lane);
        uint4 v3 = __ldg(base + (size_t)(p3 & 0xFFFF) * 32 + lane);
        float w0 = sw[warp][(p0 >> 16) * 8 + h0];
        float w1 = sw[warp][(p1 >> 16) * 8 + h0];
        float w2 = sw[warp][(p2 >> 16) * 8 + h0];
        float w3 = sw[warp][(p3 >> 16) * 8 + h0];
        const uint32_t* u0 = &v0.x;
        const uint32_t* u1 = &v1.x;
        const uint32_t* u2 = &v2.x;
        const uint32_t* u3 = &v3.x;
#pragma unroll
        for (int q = 0; q < 4; q++) {
            float2 f0 = __half22float2(*(const __half2*)&u0[q]);
            float2 f1 = __half22float2(*(const __half2*)&u1[q]);
            float2 f2 = __half22float2(*(const __half2*)&u2[q]);
            float2 f3 = __half22float2(*(const __half2*)&u3[q]);
            acc[q * 2]     += w0 * f0.x + w1 * f1.x + w2 * f2.x + w3 * f3.x;
            acc[q * 2 + 1] += w0 * f0.y + w1 * f1.y + w2 * f2.y + w3 * f3.y;
        }
    }
    for (; i < deg; i++) {
        int p0 = g_csr[off + i];
        uint4 v0 = __ldg(base + (size_t)(p0 & 0xFFFF) * 32 + lane);
        float w0 = sw[warp][(p0 >> 16) * 8 + h0];
        const uint32_t* u0 = &v0.x;
#pragma unroll
        for (int q = 0; q < 4; q++) {
            float2 f0 = __half22float2(*(const __half2*)&u0[q]);
            acc[q * 2]     += w0 * f0.x;
            acc[q * 2 + 1] += w0 * f0.y;
        }
    }

    float4* out = (float4*)(rst + (size_t)d * HD) + lane * 2;
    out[0] = make_float4(acc[0], acc[1], acc[2], acc[3]);
    out[1] = make_float4(acc[4], acc[5], acc[6], acc[7]);
}

// ---------------- launch ---------------------------------------------------
extern "C" void kernel_launch(void* const* d_in, const int* in_sizes, int n_in,
                              void* d_out, int out_size) {
    const float* feat   = (const float*)d_in[0];   // [N, 256]
    const float* fc_w   = (const float*)d_in[1];   // [256, 256]
    const float* emb    = (const float*)d_in[2];   // [5, 8]
    const int*   e_feat = (const int*)d_in[3];     // [E]
    const int*   src    = (const int*)d_in[4];     // [E]
    const int*   dst    = (const int*)d_in[5];     // [E]

    float* out_rst  = (float*)d_out;                           // [N, 8, 32]
    float* out_attn = (float*)d_out + (size_t)N_NODES * HD;    // [E, 8]

    // one-time host-side resources (created on the uncaptured correctness call)
    static cudaStream_t s2 = nullptr;
    static cudaEvent_t evFork = nullptr, evJoin = nullptr;
    if (!s2) {
        cudaStreamCreateWithFlags(&s2, cudaStreamNonBlocking);
        cudaEventCreateWithFlags(&evFork, cudaEventDisableTiming);
        cudaEventCreateWithFlags(&evJoin, cudaEventDisableTiming);
    }

    void* cnt_ptr = nullptr;
    void* fs_ptr  = nullptr;
    cudaGetSymbolAddress(&cnt_ptr, g_cnt);
    cudaGetSymbolAddress(&fs_ptr, g_feat_src);

    // fork side stream off the main (capture) stream
    cudaEventRecord(evFork, 0);
    cudaStreamWaitEvent(s2, evFork, 0);

    // ---- main stream: GEMM ----
    {
        dim3 grid((N_NODES + 127) / 128, HD / 64);
        gemm_bf16x3_kernel<<<grid, 256>>>(feat, fc_w, (__half*)fs_ptr, N_NODES);
    }

    // ---- side stream: edge pipeline ----
    cudaMemsetAsync(cnt_ptr, 0, (size_t)N_NODES * NUM_ET * sizeof(int), s2);
    count_kernel<<<(N_EDGES / 4 + 255) / 256, 256, 0, s2>>>(dst, e_feat);
    offsets_softmax_kernel<<<(N_NODES + 255) / 256, 256, 0, s2>>>(emb);
    scatter_attn_kernel<<<(N_EDGES / 4 + 255) / 256, 256, 0, s2>>>(src, dst, e_feat, out_attn);

    // join
    cudaEventRecord(evJoin, s2);
    cudaStreamWaitEvent(0, evJoin, 0);

    // ---- main stream: aggregation (needs GEMM + CSR) ----
    agg_csr_kernel<<<(N_NODES + 7) / 8, 256>>>(out_rst);
}

// round 5
// speedup vs baseline: 1.1126x; 1.1126x over previous
#include <cuda_runtime.h>
#include <cuda_bf16.h>
#include <cuda_fp16.h>
#include <math.h>
#include <stddef.h>
#include <stdint.h>

#define N_NODES 50000
#define N_EDGES 800000
#define IN_FEATS 256
#define HD 256          // NUM_HEADS * OUT_FEATS
#define NUM_HEADS 8
#define OUT_FEATS 32
#define NUM_ET 5

// ---------------- scratch (static device globals; no allocation) ----------
__device__ __half g_feat_src[(size_t)N_NODES * HD];         // 25.6 MB (fp16)
__device__ int    g_cnt[(size_t)N_NODES * NUM_ET];          // 1 MB
__device__ float  g_w[(size_t)N_NODES * NUM_ET * NUM_HEADS];// 8 MB
__device__ int    g_off[N_NODES];
__device__ int    g_deg[N_NODES];
__device__ int    g_cur[N_NODES];
__device__ int2   g_csr2[N_EDGES];                          // {src|t<<16, e}
__device__ int    g_total;

// =====================================================================
// 1) GEMM: C[M,256](fp16) = A[M,256]*B[256,256]^T, split-bf16 x3 MMA.
//    BM=128, BN=64, BK=32, 256 threads, 8 warps (4Mx2N), warp 32x32.
//    Register-prefetch pipeline: next k-tile loads issued before MMAs.
// =====================================================================
__device__ __forceinline__ void mma_bf16(float* c, const uint32_t* a, const uint32_t* b) {
    asm volatile(
        "mma.sync.aligned.m16n8k16.row.col.f32.bf16.bf16.f32 "
        "{%0,%1,%2,%3},{%4,%5,%6,%7},{%8,%9},{%0,%1,%2,%3};\n"
        : "+f"(c[0]), "+f"(c[1]), "+f"(c[2]), "+f"(c[3])
        : "r"(a[0]), "r"(a[1]), "r"(a[2]), "r"(a[3]), "r"(b[0]), "r"(b[1]));
}

__device__ __forceinline__ void split_store(__nv_bfloat16* ph, __nv_bfloat16* pl, float4 v) {
    __nv_bfloat162 h01, h23, l01, l23;
    h01.x = __float2bfloat16(v.x);
    h01.y = __float2bfloat16(v.y);
    h23.x = __float2bfloat16(v.z);
    h23.y = __float2bfloat16(v.w);
    l01.x = __float2bfloat16(v.x - __bfloat162float(h01.x));
    l01.y = __float2bfloat16(v.y - __bfloat162float(h01.y));
    l23.x = __float2bfloat16(v.z - __bfloat162float(h23.x));
    l23.y = __float2bfloat16(v.w - __bfloat162float(h23.y));
    *(__nv_bfloat162*)(ph)     = h01;
    *(__nv_bfloat162*)(ph + 2) = h23;
    *(__nv_bfloat162*)(pl)     = l01;
    *(__nv_bfloat162*)(pl + 2) = l23;
}

__global__ __launch_bounds__(256) void gemm_bf16x3_kernel(
    const float* __restrict__ A, const float* __restrict__ B,
    __half* __restrict__ C, int M) {
    __shared__ __nv_bfloat16 As_h[128][40], As_l[128][40];
    __shared__ __nv_bfloat16 Bs_h[64][40],  Bs_l[64][40];

    const int tid = threadIdx.x;
    const int m0 = blockIdx.x * 128;
    const int n0 = blockIdx.y * 64;
    const int warp = tid >> 5, lane = tid & 31;
    const int wm0 = (warp >> 1) * 32, wn0 = (warp & 1) * 32;
    const int g = lane >> 2, tg = lane & 3;

    // per-thread load coordinates
    const int arow[4] = { (tid + 0)   >> 3, (tid + 256) >> 3,
                          (tid + 512) >> 3, (tid + 768) >> 3 };
    const int ac4 = (tid & 7) * 4;
    const int brow[2] = { (tid + 0) >> 3, (tid + 256) >> 3 };

    float acc[2][4][4];
#pragma unroll
    for (int i = 0; i < 2; i++)
#pragma unroll
        for (int j = 0; j < 4; j++)
#pragma unroll
            for (int q = 0; q < 4; q++) acc[i][j][q] = 0.f;

    // prologue: prefetch k0 = 0 tiles into registers
    float4 pa[4], pb[2];
#pragma unroll
    for (int r = 0; r < 4; r++) {
        pa[r] = make_float4(0.f, 0.f, 0.f, 0.f);
        if (m0 + arow[r] < M)
            pa[r] = __ldg((const float4*)(A + (size_t)(m0 + arow[r]) * 256 + ac4));
    }
#pragma unroll
    for (int r = 0; r < 2; r++)
        pb[r] = __ldg((const float4*)(B + (size_t)(n0 + brow[r]) * 256 + ac4));

#pragma unroll 1
    for (int k0 = 0; k0 < 256; k0 += 32) {
        // stage current tile into smem
#pragma unroll
        for (int r = 0; r < 4; r++)
            split_store(&As_h[arow[r]][ac4], &As_l[arow[r]][ac4], pa[r]);
#pragma unroll
        for (int r = 0; r < 2; r++)
            split_store(&Bs_h[brow[r]][ac4], &Bs_l[brow[r]][ac4], pb[r]);
        __syncthreads();

        // prefetch next tile (overlaps with MMA below)
        if (k0 + 32 < 256) {
            const int kn = k0 + 32;
#pragma unroll
            for (int r = 0; r < 4; r++)
                if (m0 + arow[r] < M)
                    pa[r] = __ldg((const float4*)(A + (size_t)(m0 + arow[r]) * 256 + kn + ac4));
#pragma unroll
            for (int r = 0; r < 2; r++)
                pb[r] = __ldg((const float4*)(B + (size_t)(n0 + brow[r]) * 256 + kn + ac4));
        }

#pragma unroll
        for (int kf = 0; kf < 2; kf++) {
            const int kA = kf * 16 + tg * 2;
            uint32_t ah[2][4], al[2][4], bh[4][2], bl[4][2];
#pragma unroll
            for (int i = 0; i < 2; i++) {
                int r0 = wm0 + i * 16 + g;
                ah[i][0] = *(const uint32_t*)&As_h[r0][kA];
                ah[i][1] = *(const uint32_t*)&As_h[r0 + 8][kA];
                ah[i][2] = *(const uint32_t*)&As_h[r0][kA + 8];
                ah[i][3] = *(const uint32_t*)&As_h[r0 + 8][kA + 8];
                al[i][0] = *(const uint32_t*)&As_l[r0][kA];
                al[i][1] = *(const uint32_t*)&As_l[r0 + 8][kA];
                al[i][2] = *(const uint32_t*)&As_l[r0][kA + 8];
                al[i][3] = *(const uint32_t*)&As_l[r0 + 8][kA + 8];
            }
#pragma unroll
            for (int j = 0; j < 4; j++) {
                int c0 = wn0 + j * 8 + g;
                bh[j][0] = *(const uint32_t*)&Bs_h[c0][kA];
                bh[j][1] = *(const uint32_t*)&Bs_h[c0][kA + 8];
                bl[j][0] = *(const uint32_t*)&Bs_l[c0][kA];
                bl[j][1] = *(const uint32_t*)&Bs_l[c0][kA + 8];
            }
#pragma unroll
            for (int i = 0; i < 2; i++)
#pragma unroll
                for (int j = 0; j < 4; j++) {
                    mma_bf16(acc[i][j], ah[i], bh[j]);
                    mma_bf16(acc[i][j], ah[i], bl[j]);
                    mma_bf16(acc[i][j], al[i], bh[j]);
                }
        }
        __syncthreads();
    }

#pragma unroll
    for (int i = 0; i < 2; i++)
#pragma unroll
        for (int j = 0; j < 4; j++) {
            int m_lo = m0 + wm0 + i * 16 + g;
            int col  = n0 + wn0 + j * 8 + tg * 2;
            if (m_lo < M)
                *(__half2*)(C + (size_t)m_lo * 256 + col) =
                    __floats2half2_rn(acc[i][j][0], acc[i][j][1]);
            if (m_lo + 8 < M)
                *(__half2*)(C + (size_t)(m_lo + 8) * 256 + col) =
                    __floats2half2_rn(acc[i][j][2], acc[i][j][3]);
        }
}

// ---------------- 2) histogram, 1 edge/thread (+ clear g_total) -----------
__global__ void count_kernel(const int* __restrict__ dst,
                             const int* __restrict__ ef) {
    int i = blockIdx.x * blockDim.x + threadIdx.x;
    if (i == 0) g_total = 0;
    if (i < N_EDGES)
        atomicAdd(&g_cnt[(size_t)dst[i] * NUM_ET + ef[i]], 1);
}

// ---------------- 3) fused CSR offsets + per-node softmax table -----------
__global__ void offsets_softmax_kernel(const float* __restrict__ emb) {
    int n = blockIdx.x * blockDim.x + threadIdx.x;
    int lane = threadIdx.x & 31;

    int c[NUM_ET];
    int deg = 0;
    if (n < N_NODES) {
#pragma unroll
        for (int t = 0; t < NUM_ET; t++) {
            c[t] = g_cnt[(size_t)n * NUM_ET + t];
            deg += c[t];
        }
    }
    int incl = deg;
#pragma unroll
    for (int o = 1; o < 32; o <<= 1) {
        int v = __shfl_up_sync(0xffffffffu, incl, o);
        if (lane >= o) incl += v;
    }
    int total = __shfl_sync(0xffffffffu, incl, 31);
    int base = 0;
    if (lane == 0) base = atomicAdd(&g_total, total);
    base = __shfl_sync(0xffffffffu, base, 0);

    if (n < N_NODES) {
        int off = base + incl - deg;
        g_off[n] = off;
        g_cur[n] = off;
        g_deg[n] = deg;

#pragma unroll
        for (int h = 0; h < NUM_HEADS; h++) {
            float ev[NUM_ET];
            float m = -INFINITY;
#pragma unroll
            for (int t = 0; t < NUM_ET; t++) {
                ev[t] = __ldg(emb + t * NUM_HEADS + h);
                if (c[t] > 0) m = fmaxf(m, ev[t]);
            }
            float ex[NUM_ET];
            float denom = 0.f;
#pragma unroll
            for (int t = 0; t < NUM_ET; t++) {
                ex[t] = expf(ev[t] - m);
                denom += (float)c[t] * ex[t];
            }
            float inv = 1.f / denom;   // NaN only for deg==0 nodes (unread)
#pragma unroll
            for (int t = 0; t < NUM_ET; t++)
                g_w[((size_t)n * NUM_ET + t) * NUM_HEADS + h] = ex[t] * inv;
        }
    }
}

// ---------------- 4) scatter edges into CSR (slim), 1 edge/thread ---------
__global__ void scatter_csr_kernel(const int* __restrict__ src,
                                   const int* __restrict__ dst,
                                   const int* __restrict__ ef) {
    int e = blockIdx.x * blockDim.x + threadIdx.x;
    if (e >= N_EDGES) return;
    int s = src[e];
    int d = dst[e];
    int t = ef[e];
    int pos = atomicAdd(&g_cur[d], 1);
    g_csr2[pos] = make_int2(s | (t << 16), e);
}

// ---------------- 5) CSR aggregation + fused attn write -------------------
__global__ __launch_bounds__(256) void agg_csr_kernel(float* __restrict__ rst,
                                                      float* __restrict__ attn_out) {
    __shared__ float sw[8][NUM_ET * NUM_HEADS];
    const int warp = threadIdx.x >> 5;
    const int lane = threadIdx.x & 31;
    const int d = blockIdx.x * 8 + warp;
    if (d >= N_NODES) return;

    sw[warp][lane] = g_w[(size_t)d * 40 + lane];
    if (lane < 8) sw[warp][32 + lane] = g_w[(size_t)d * 40 + 32 + lane];
    __syncwarp();

    const int off = g_off[d];
    const int deg = g_deg[d];
    const int h0 = lane >> 2;          // head of this lane's 8 feature cols
    const int sel = lane >> 3;         // which of 4 unrolled edges this lane's
    const int hl  = lane & 7;          //   attn-write covers
    const uint4* base = (const uint4*)g_feat_src;

    float acc[8];
#pragma unroll
    for (int q = 0; q < 8; q++) acc[q] = 0.f;

    int i = 0;
    for (; i + 4 <= deg; i += 4) {
        // uniform (broadcast) CSR loads: every lane sees all 4 edges
        int2 q0 = g_csr2[off + i];
        int2 q1 = g_csr2[off + i + 1];
        int2 q2 = g_csr2[off + i + 2];
        int2 q3 = g_csr2[off + i + 3];
        uint4 v0 = __ldg(base + (size_t)(q0.x & 0xFFFF) * 32 + lane);
        uint4 v1 = __ldg(base + (size_t)(q1.x & 0xFFFF) * 32 + lane);
        uint4 v2 = __ldg(base + (size_t)(q2.x & 0xFFFF) * 32 + lane);
        uint4 v3 = __ldg(base + (size_t)(q3.x & 0xFFFF) * 32 + lane);
        float w0 = sw[warp][(q0.x >> 16) * 8 + h0];
        float w1 = sw[warp][(q1.x >> 16) * 8 + h0];
        float w2 = sw[warp][(q2.x >> 16) * 8 + h0];
        float w3 = sw[warp][(q3.x >> 16) * 8 + h0];
        const uint32_t* u0 = &v0.x;
        const uint32_t* u1 = &v1.x;
        const uint32_t* u2 = &v2.x;
        const uint32_t* u3 = &v3.x;
#pragma unroll
        for (int q = 0; q < 4; q++) {
            float2 f0 = __half22float2(*(const __half2*)&u0[q]);
            float2 f1 = __half22float2(*(const __half2*)&u1[q]);
            float2 f2 = __half22float2(*(const __half2*)&u2[q]);
            float2 f3 = __half22float2(*(const __half2*)&u3[q]);
            acc[q * 2]     += w0 * f0.x + w1 * f1.x + w2 * f2.x + w3 * f3.x;
            acc[q * 2 + 1] += w0 * f0.y + w1 * f1.y + w2 * f2.y + w3 * f3.y;
        }
        // fused attn write: lane group `sel` covers edge `sel`'s 8 heads
        int ee = (sel == 0) ? q0.y : (sel == 1) ? q1.y : (sel == 2) ? q2.y : q3.y;
        int tt = ((sel == 0) ? q0.x : (sel == 1) ? q1.x : (sel == 2) ? q2.x : q3.x) >> 16;
        attn_out[(size_t)ee * NUM_HEADS + hl] = sw[warp][tt * 8 + hl];
    }
    for (; i < deg; i++) {
        int2 q0 = g_csr2[off + i];
        uint4 v0 = __ldg(base + (size_t)(q0.x & 0xFFFF) * 32 + lane);
        float w0 = sw[warp][(q0.x >> 16) * 8 + h0];
        const uint32_t* u0 = &v0.x;
#pragma unroll
        for (int q = 0; q < 4; q++) {
            float2 f0 = __half22float2(*(const __half2*)&u0[q]);
            acc[q * 2]     += w0 * f0.x;
            acc[q * 2 + 1] += w0 * f0.y;
        }
        if (lane < 8)
            attn_out[(size_t)q0.y * NUM_HEADS + lane] = sw[warp][(q0.x >> 16) * 8 + lane];
    }

    float4* out = (float4*)(rst + (size_t)d * HD) + lane * 2;
    out[0] = make_float4(acc[0], acc[1], acc[2], acc[3]);
    out[1] = make_float4(acc[4], acc[5], acc[6], acc[7]);
}

// ---------------- launch ---------------------------------------------------
extern "C" void kernel_launch(void* const* d_in, const int* in_sizes, int n_in,
                              void* d_out, int out_size) {
    const float* feat   = (const float*)d_in[0];   // [N, 256]
    const float* fc_w   = (const float*)d_in[1];   // [256, 256]
    const float* emb    = (const float*)d_in[2];   // [5, 8]
    const int*   e_feat = (const int*)d_in[3];     // [E]
    const int*   src    = (const int*)d_in[4];     // [E]
    const int*   dst    = (const int*)d_in[5];     // [E]

    float* out_rst  = (float*)d_out;                           // [N, 8, 32]
    float* out_attn = (float*)d_out + (size_t)N_NODES * HD;    // [E, 8]

    void* cnt_ptr = nullptr;
    void* fs_ptr  = nullptr;
    cudaGetSymbolAddress(&cnt_ptr, g_cnt);
    cudaGetSymbolAddress(&fs_ptr, g_feat_src);

    cudaMemsetAsync(cnt_ptr, 0, (size_t)N_NODES * NUM_ET * sizeof(int));

    // 1) GEMM (tensor cores, split-bf16 x3, reg-prefetch pipeline)
    {
        dim3 grid((N_NODES + 127) / 128, HD / 64);
        gemm_bf16x3_kernel<<<grid, 256>>>(feat, fc_w, (__half*)fs_ptr, N_NODES);
    }
    // 2) histogram (+ clears g_total)
    count_kernel<<<(N_EDGES + 255) / 256, 256>>>(dst, e_feat);
    // 3) fused offsets + softmax
    offsets_softmax_kernel<<<(N_NODES + 255) / 256, 256>>>(emb);
    // 4) slim scatter to CSR
    scatter_csr_kernel<<<(N_EDGES + 255) / 256, 256>>>(src, dst, e_feat);
    // 5) aggregation + fused attn write
    agg_csr_kernel<<<(N_NODES + 7) / 8, 256>>>(out_rst, out_attn);
}

// round 6
// speedup vs baseline: 1.2369x; 1.1118x over previous
#include <cuda_runtime.h>
#include <cuda_bf16.h>
#include <cuda_fp16.h>
#include <math.h>
#include <stddef.h>
#include <stdint.h>

#define N_NODES 50000
#define N_EDGES 800000
#define IN_FEATS 256
#define HD 256          // NUM_HEADS * OUT_FEATS
#define NUM_HEADS 8
#define OUT_FEATS 32
#define NUM_ET 5

// ---------------- scratch (static device globals; no allocation) ----------
__device__ __half g_feat_src[(size_t)N_NODES * HD];         // 25.6 MB (fp16)
__device__ int    g_cnt[(size_t)N_NODES * NUM_ET];          // 1 MB (BSS zero)
__device__ float  g_w[(size_t)N_NODES * NUM_ET * NUM_HEADS];// 8 MB
__device__ int    g_off[N_NODES];
__device__ int    g_deg[N_NODES];
__device__ int    g_cur[N_NODES];
__device__ int2   g_csr2[N_EDGES];                          // {src|t<<16, e}
__device__ int    g_total;

// =====================================================================
// 1) GEMM: C[M,256](fp16) = A[M,256]*B[256,256]^T, single-pass tf32 MMA.
//    BM=128, BN=128, BK=32, 256 threads, 8 warps (4Mx2N), warp 32x64.
//    Register-prefetch pipeline over k tiles.
// =====================================================================
__device__ __forceinline__ void mma_tf32(float* c, const uint32_t* a,
                                         uint32_t b0, uint32_t b1) {
    asm volatile(
        "mma.sync.aligned.m16n8k8.row.col.f32.tf32.tf32.f32 "
        "{%0,%1,%2,%3},{%4,%5,%6,%7},{%8,%9},{%0,%1,%2,%3};\n"
        : "+f"(c[0]), "+f"(c[1]), "+f"(c[2]), "+f"(c[3])
        : "r"(a[0]), "r"(a[1]), "r"(a[2]), "r"(a[3]), "r"(b0), "r"(b1));
}

__device__ __forceinline__ float tf32r(float x) {
    float y;
    asm("cvt.rna.tf32.f32 %0, %1;" : "=f"(y) : "f"(x));
    return y;
}

__device__ __forceinline__ void cvt_store4(float* p, float4 v) {
    p[0] = tf32r(v.x);
    p[1] = tf32r(v.y);
    p[2] = tf32r(v.z);
    p[3] = tf32r(v.w);
}

__global__ __launch_bounds__(256) void gemm_tf32_kernel(
    const float* __restrict__ A, const float* __restrict__ B,
    __half* __restrict__ C, int M) {
    __shared__ float As[128][36];
    __shared__ float Bs[128][36];

    const int tid = threadIdx.x;
    const int m0 = blockIdx.x * 128;
    const int n0 = blockIdx.y * 128;
    const int warp = tid >> 5, lane = tid & 31;
    const int wm0 = (warp >> 1) * 32;     // warp m origin (4 groups of 32)
    const int wn0 = (warp & 1) * 64;      // warp n origin (2 groups of 64)
    const int g = lane >> 2, tg = lane & 3;

    // per-thread load coordinates (A and B tiles are both 128x32)
    const int row0 = tid >> 3;            // + r*32
    const int ac4 = (tid & 7) * 4;

    float acc[2][8][4];
#pragma unroll
    for (int i = 0; i < 2; i++)
#pragma unroll
        for (int j = 0; j < 8; j++)
#pragma unroll
            for (int q = 0; q < 4; q++) acc[i][j][q] = 0.f;

    // prologue: prefetch k0 = 0 tiles into registers
    float4 pa[4], pb[4];
#pragma unroll
    for (int r = 0; r < 4; r++) {
        int row = row0 + r * 32;
        pa[r] = make_float4(0.f, 0.f, 0.f, 0.f);
        if (m0 + row < M)
            pa[r] = __ldg((const float4*)(A + (size_t)(m0 + row) * 256 + ac4));
        pb[r] = __ldg((const float4*)(B + (size_t)(n0 + row) * 256 + ac4));
    }

#pragma unroll 1
    for (int k0 = 0; k0 < 256; k0 += 32) {
#pragma unroll
        for (int r = 0; r < 4; r++) {
            int row = row0 + r * 32;
            cvt_store4(&As[row][ac4], pa[r]);
            cvt_store4(&Bs[row][ac4], pb[r]);
        }
        __syncthreads();

        if (k0 + 32 < 256) {
            const int kn = k0 + 32;
#pragma unroll
            for (int r = 0; r < 4; r++) {
                int row = row0 + r * 32;
                if (m0 + row < M)
                    pa[r] = __ldg((const float4*)(A + (size_t)(m0 + row) * 256 + kn + ac4));
                pb[r] = __ldg((const float4*)(B + (size_t)(n0 + row) * 256 + kn + ac4));
            }
        }

#pragma unroll
        for (int kf = 0; kf < 4; kf++) {
            const int kk = kf * 8;
            uint32_t a[2][4], b[8][2];
#pragma unroll
            for (int i = 0; i < 2; i++) {
                int r0 = wm0 + i * 16 + g;
                a[i][0] = *(const uint32_t*)&As[r0][kk + tg];
                a[i][1] = *(const uint32_t*)&As[r0 + 8][kk + tg];
                a[i][2] = *(const uint32_t*)&As[r0][kk + tg + 4];
                a[i][3] = *(const uint32_t*)&As[r0 + 8][kk + tg + 4];
            }
#pragma unroll
            for (int j = 0; j < 8; j++) {
                int c0 = wn0 + j * 8 + g;
                b[j][0] = *(const uint32_t*)&Bs[c0][kk + tg];
                b[j][1] = *(const uint32_t*)&Bs[c0][kk + tg + 4];
            }
#pragma unroll
            for (int i = 0; i < 2; i++)
#pragma unroll
                for (int j = 0; j < 8; j++)
                    mma_tf32(acc[i][j], a[i], b[j][0], b[j][1]);
        }
        __syncthreads();
    }

#pragma unroll
    for (int i = 0; i < 2; i++)
#pragma unroll
        for (int j = 0; j < 8; j++) {
            int m_lo = m0 + wm0 + i * 16 + g;
            int col  = n0 + wn0 + j * 8 + tg * 2;
            if (m_lo < M)
                *(__half2*)(C + (size_t)m_lo * 256 + col) =
                    __floats2half2_rn(acc[i][j][0], acc[i][j][1]);
            if (m_lo + 8 < M)
                *(__half2*)(C + (size_t)(m_lo + 8) * 256 + col) =
                    __floats2half2_rn(acc[i][j][2], acc[i][j][3]);
        }
}

// ---------------- 2) histogram, 1 edge/thread (+ clear g_total) -----------
__global__ void count_kernel(const int* __restrict__ dst,
                             const int* __restrict__ ef) {
    int i = blockIdx.x * blockDim.x + threadIdx.x;
    if (i == 0) g_total = 0;
    if (i < N_EDGES)
        atomicAdd(&g_cnt[(size_t)dst[i] * NUM_ET + ef[i]], 1);
}

// ------- 3) fused CSR offsets + softmax (+ re-zero g_cnt for next run) ----
__global__ void offsets_softmax_kernel(const float* __restrict__ emb) {
    int n = blockIdx.x * blockDim.x + threadIdx.x;
    int lane = threadIdx.x & 31;

    int c[NUM_ET];
    int deg = 0;
    if (n < N_NODES) {
#pragma unroll
        for (int t = 0; t < NUM_ET; t++) {
            c[t] = g_cnt[(size_t)n * NUM_ET + t];
            deg += c[t];
        }
        // restore zeroed state for the next graph replay (removes memset)
#pragma unroll
        for (int t = 0; t < NUM_ET; t++)
            g_cnt[(size_t)n * NUM_ET + t] = 0;
    }
    int incl = deg;
#pragma unroll
    for (int o = 1; o < 32; o <<= 1) {
        int v = __shfl_up_sync(0xffffffffu, incl, o);
        if (lane >= o) incl += v;
    }
    int total = __shfl_sync(0xffffffffu, incl, 31);
    int base = 0;
    if (lane == 0) base = atomicAdd(&g_total, total);
    base = __shfl_sync(0xffffffffu, base, 0);

    if (n < N_NODES) {
        int off = base + incl - deg;
        g_off[n] = off;
        g_cur[n] = off;
        g_deg[n] = deg;

#pragma unroll
        for (int h = 0; h < NUM_HEADS; h++) {
            float ev[NUM_ET];
            float m = -INFINITY;
#pragma unroll
            for (int t = 0; t < NUM_ET; t++) {
                ev[t] = __ldg(emb + t * NUM_HEADS + h);
                if (c[t] > 0) m = fmaxf(m, ev[t]);
            }
            float ex[NUM_ET];
            float denom = 0.f;
#pragma unroll
            for (int t = 0; t < NUM_ET; t++) {
                ex[t] = expf(ev[t] - m);
                denom += (float)c[t] * ex[t];
            }
            float inv = 1.f / denom;   // NaN only for deg==0 nodes (unread)
#pragma unroll
            for (int t = 0; t < NUM_ET; t++)
                g_w[((size_t)n * NUM_ET + t) * NUM_HEADS + h] = ex[t] * inv;
        }
    }
}

// ---------------- 4) scatter edges into CSR (slim), 1 edge/thread ---------
__global__ void scatter_csr_kernel(const int* __restrict__ src,
                                   const int* __restrict__ dst,
                                   const int* __restrict__ ef) {
    int e = blockIdx.x * blockDim.x + threadIdx.x;
    if (e >= N_EDGES) return;
    int s = src[e];
    int d = dst[e];
    int t = ef[e];
    int pos = atomicAdd(&g_cur[d], 1);
    g_csr2[pos] = make_int2(s | (t << 16), e);
}

// ---------------- 5) CSR aggregation + fused attn write (8-deep MLP) ------
__global__ __launch_bounds__(256) void agg_csr_kernel(float* __restrict__ rst,
                                                      float* __restrict__ attn_out) {
    __shared__ float sw[8][NUM_ET * NUM_HEADS];
    const int warp = threadIdx.x >> 5;
    const int lane = threadIdx.x & 31;
    const int d = blockIdx.x * 8 + warp;
    if (d >= N_NODES) return;

    sw[warp][lane] = g_w[(size_t)d * 40 + lane];
    if (lane < 8) sw[warp][32 + lane] = g_w[(size_t)d * 40 + 32 + lane];
    __syncwarp();

    const int off = g_off[d];
    const int deg = g_deg[d];
    const int h0 = lane >> 2;          // head of this lane's 8 feature cols
    const int sel = lane >> 3;         // attn-write edge selector (0..3)
    const int hl  = lane & 7;          // attn-write head
    const uint4* base = (const uint4*)g_feat_src;

    float acc[8];
#pragma unroll
    for (int q = 0; q < 8; q++) acc[q] = 0.f;

    int i = 0;
    for (; i + 8 <= deg; i += 8) {
        int2 qq[8];
        uint4 vv[8];
        float ww[8];
#pragma unroll
        for (int u = 0; u < 8; u++) qq[u] = g_csr2[off + i + u];
#pragma unroll
        for (int u = 0; u < 8; u++)
            vv[u] = __ldg(base + (size_t)(qq[u].x & 0xFFFF) * 32 + lane);
#pragma unroll
        for (int u = 0; u < 8; u++) ww[u] = sw[warp][(qq[u].x >> 16) * 8 + h0];
#pragma unroll
        for (int u = 0; u < 8; u++) {
            const uint32_t* uv = &vv[u].x;
#pragma unroll
            for (int q = 0; q < 4; q++) {
                float2 f = __half22float2(*(const __half2*)&uv[q]);
                acc[q * 2]     += ww[u] * f.x;
                acc[q * 2 + 1] += ww[u] * f.y;
            }
        }
        // fused attn writes: 2 batches of 4 edges, lane group sel -> edge
        {
            int2 qa = qq[sel];
            int2 qb = qq[sel + 4];
            attn_out[(size_t)qa.y * NUM_HEADS + hl] = sw[warp][(qa.x >> 16) * 8 + hl];
            attn_out[(size_t)qb.y * NUM_HEADS + hl] = sw[warp][(qb.x >> 16) * 8 + hl];
        }
    }
    for (; i + 4 <= deg; i += 4) {
        int2 qq[4];
        uint4 vv[4];
#pragma unroll
        for (int u = 0; u < 4; u++) qq[u] = g_csr2[off + i + u];
#pragma unroll
        for (int u = 0; u < 4; u++)
            vv[u] = __ldg(base + (size_t)(qq[u].x & 0xFFFF) * 32 + lane);
#pragma unroll
        for (int u = 0; u < 4; u++) {
            float w = sw[warp][(qq[u].x >> 16) * 8 + h0];
            const uint32_t* uv = &vv[u].x;
#pragma unroll
            for (int q = 0; q < 4; q++) {
                float2 f = __half22float2(*(const __half2*)&uv[q]);
                acc[q * 2]     += w * f.x;
                acc[q * 2 + 1] += w * f.y;
            }
        }
        int2 qa = qq[sel];
        attn_out[(size_t)qa.y * NUM_HEADS + hl] = sw[warp][(qa.x >> 16) * 8 + hl];
    }
    for (; i < deg; i++) {
        int2 q0 = g_csr2[off + i];
        uint4 v0 = __ldg(base + (size_t)(q0.x & 0xFFFF) * 32 + lane);
        float w0 = sw[warp][(q0.x >> 16) * 8 + h0];
        const uint32_t* u0 = &v0.x;
#pragma unroll
        for (int q = 0; q < 4; q++) {
            float2 f0 = __half22float2(*(const __half2*)&u0[q]);
            acc[q * 2]     += w0 * f0.x;
            acc[q * 2 + 1] += w0 * f0.y;
        }
        if (lane < 8)
            attn_out[(size_t)q0.y * NUM_HEADS + lane] = sw[warp][(q0.x >> 16) * 8 + lane];
    }

    float4* out = (float4*)(rst + (size_t)d * HD) + lane * 2;
    out[0] = make_float4(acc[0], acc[1], acc[2], acc[3]);
    out[1] = make_float4(acc[4], acc[5], acc[6], acc[7]);
}

// ---------------- launch ---------------------------------------------------
extern "C" void kernel_launch(void* const* d_in, const int* in_sizes, int n_in,
                              void* d_out, int out_size) {
    const float* feat   = (const float*)d_in[0];   // [N, 256]
    const float* fc_w   = (const float*)d_in[1];   // [256, 256]
    const float* emb    = (const float*)d_in[2];   // [5, 8]
    const int*   e_feat = (const int*)d_in[3];     // [E]
    const int*   src    = (const int*)d_in[4];     // [E]
    const int*   dst    = (const int*)d_in[5];     // [E]

    float* out_rst  = (float*)d_out;                           // [N, 8, 32]
    float* out_attn = (float*)d_out + (size_t)N_NODES * HD;    // [E, 8]

    void* fs_ptr = nullptr;
    cudaGetSymbolAddress(&fs_ptr, g_feat_src);

    // 1) GEMM (tensor cores, tf32 single pass)
    {
        dim3 grid((N_NODES + 127) / 128, HD / 128);
        gemm_tf32_kernel<<<grid, 256>>>(feat, fc_w, (__half*)fs_ptr, N_NODES);
    }
    // 2) histogram (+ clears g_total)
    count_kernel<<<(N_EDGES + 255) / 256, 256>>>(dst, e_feat);
    // 3) fused offsets + softmax (+ re-zeroes g_cnt)
    offsets_softmax_kernel<<<(N_NODES + 255) / 256, 256>>>(emb);
    // 4) slim scatter to CSR
    scatter_csr_kernel<<<(N_EDGES + 255) / 256, 256>>>(src, dst, e_feat);
    // 5) aggregation + fused attn write
    agg_csr_kernel<<<(N_NODES + 7) / 8, 256>>>(out_rst, out_attn);
}